// round 1
// baseline (speedup 1.0000x reference)
#include <cuda_runtime.h>
#include <cuda_bf16.h>
#include <math.h>

// Problem constants
#define BB 4
#define SS 2048
#define DD 768
#define HH 12
#define HD 64
#define FF 3072
#define NTOK (BB*SS)          // 8192
#define EPS 1e-5f

// ---------------- scratch (static device globals; no allocation) -------------
__device__ float g_h   [(size_t)NTOK*DD];          // LN1 out
__device__ float g_wqkv[(size_t)DD*3*DD];          // repacked [D, 3D] weights
__device__ float g_bqkv[3*DD];                     // repacked bias
__device__ float g_qkv [(size_t)NTOK*3*DD];        // [n, 2304] : q|k|v, col=h*64+e
__device__ float g_sc  [(size_t)BB*HH*SS*SS];      // attention scores / probs
__device__ float g_o   [(size_t)NTOK*DD];          // attention out [b,s,h,e]
__device__ float g_a   [(size_t)NTOK*DD];          // after Wo
__device__ float g_h2  [(size_t)NTOK*DD];          // LN2 out
__device__ float g_f   [(size_t)NTOK*FF];          // gelu(FFN1)

// ---------------- reductions -------------------------------------------------
__device__ __forceinline__ float block_sum256(float v, float* sm) {
    __syncthreads();
    #pragma unroll
    for (int o = 16; o > 0; o >>= 1) v += __shfl_xor_sync(0xffffffffu, v, o);
    int lane = threadIdx.x & 31, w = threadIdx.x >> 5;
    if (lane == 0) sm[w] = v;
    __syncthreads();
    if (w == 0) {
        v = (lane < 8) ? sm[lane] : 0.f;
        #pragma unroll
        for (int o = 4; o > 0; o >>= 1) v += __shfl_xor_sync(0xffffffffu, v, o);
        if (lane == 0) sm[0] = v;
    }
    __syncthreads();
    return sm[0];
}

__device__ __forceinline__ float block_max256(float v, float* sm) {
    __syncthreads();
    #pragma unroll
    for (int o = 16; o > 0; o >>= 1) v = fmaxf(v, __shfl_xor_sync(0xffffffffu, v, o));
    int lane = threadIdx.x & 31, w = threadIdx.x >> 5;
    if (lane == 0) sm[w] = v;
    __syncthreads();
    if (w == 0) {
        v = (lane < 8) ? sm[lane] : -3.4e38f;
        #pragma unroll
        for (int o = 4; o > 0; o >>= 1) v = fmaxf(v, __shfl_xor_sync(0xffffffffu, v, o));
        if (lane == 0) sm[0] = v;
    }
    __syncthreads();
    return sm[0];
}

// ---------------- LayerNorm (row = 768, block = 256) -------------------------
__global__ void ln_kernel(const float* __restrict__ x, const float* __restrict__ g,
                          const float* __restrict__ be, float* __restrict__ out) {
    __shared__ float sm[32];
    long row = blockIdx.x;
    const float* xr = x + row * DD;
    int t = threadIdx.x;
    float v0 = xr[t], v1 = xr[t + 256], v2 = xr[t + 512];
    float mu = block_sum256(v0 + v1 + v2, sm) * (1.f / DD);
    float d0 = v0 - mu, d1 = v1 - mu, d2 = v2 - mu;
    float var = block_sum256(d0*d0 + d1*d1 + d2*d2, sm) * (1.f / DD);
    float r = rsqrtf(var + EPS);
    float* o = out + row * DD;
    o[t]       = d0 * r * g[t]       + be[t];
    o[t + 256] = d1 * r * g[t + 256] + be[t + 256];
    o[t + 512] = d2 * r * g[t + 512] + be[t + 512];
}

// ---------------- weight repack: [H,D,HD]x3 -> [D, 3D] -----------------------
__global__ void repack_kernel(const float* __restrict__ Wq, const float* __restrict__ Wk,
                              const float* __restrict__ Wv, const float* __restrict__ bq,
                              const float* __restrict__ bk, const float* __restrict__ bv,
                              float* __restrict__ Wt, float* __restrict__ bt) {
    int idx = blockIdx.x * blockDim.x + threadIdx.x;
    if (idx < DD * 3 * DD) {
        int d = idx / (3 * DD);
        int c = idx % (3 * DD);
        int p = c / DD, r = c % DD;
        int h = r / HD, e = r % HD;
        const float* W = (p == 0) ? Wq : (p == 1) ? Wk : Wv;
        Wt[idx] = W[((long)h * DD + d) * HD + e];
    }
    if (idx < 3 * DD) {
        int p = idx / DD, r = idx % DD;
        int h = r / HD, e = r % HD;
        const float* b = (p == 0) ? bq : (p == 1) ? bk : bv;
        bt[idx] = b[h * HD + e];
    }
}

// ---------------- generic SGEMM, NN: C = alpha*(A@B) + bias, opt. GELU -------
// A: [M,K] lda   B: [K,N] ldb   C: [M,N] ldc.  Batched via blockIdx.z with
// two-level (b,h) offsets when Hh > 0.
template<int BM, int BN, int BK, int TM, int TN, int ACT>
__global__ void __launch_bounds__((BM/TM)*(BN/TN))
sgemm_nn(const float* __restrict__ A, const float* __restrict__ Bm,
         const float* __restrict__ bias, float* __restrict__ C,
         int M, int N, int K, int lda, int ldb, int ldc, float alpha,
         long sAb, long sAh, long sBb, long sBh, long sCb, long sCh, int Hh) {
    constexpr int THREADS = (BM/TM)*(BN/TN);
    if (Hh > 0) {
        int z = blockIdx.z;
        int bb = z / Hh, hh = z % Hh;
        A  += (long)bb * sAb + (long)hh * sAh;
        Bm += (long)bb * sBb + (long)hh * sBh;
        C  += (long)bb * sCb + (long)hh * sCh;
    }
    __shared__ float As[BK][BM];
    __shared__ float Bs[BK][BN];
    int tid = threadIdx.x;
    int tx = tid % (BN / TN);
    int ty = tid / (BN / TN);
    int row0 = blockIdx.y * BM;
    int col0 = blockIdx.x * BN;
    float acc[TM][TN] = {};
    constexpr int AVEC = BM * BK / (4 * THREADS);
    constexpr int BVEC = BK * BN / (4 * THREADS);
    for (int k0 = 0; k0 < K; k0 += BK) {
        #pragma unroll
        for (int i = 0; i < AVEC; i++) {
            int idx = tid + i * THREADS;
            int m  = idx / (BK / 4);
            int kk = (idx % (BK / 4)) * 4;
            float4 v = *(const float4*)&A[(long)(row0 + m) * lda + k0 + kk];
            As[kk + 0][m] = v.x; As[kk + 1][m] = v.y;
            As[kk + 2][m] = v.z; As[kk + 3][m] = v.w;
        }
        #pragma unroll
        for (int i = 0; i < BVEC; i++) {
            int idx = tid + i * THREADS;
            int kk = idx / (BN / 4);
            int n  = (idx % (BN / 4)) * 4;
            *(float4*)&Bs[kk][n] = *(const float4*)&Bm[(long)(k0 + kk) * ldb + col0 + n];
        }
        __syncthreads();
        #pragma unroll
        for (int k = 0; k < BK; k++) {
            float ra[TM], rb[TN];
            #pragma unroll
            for (int i = 0; i < TM; i++) ra[i] = As[k][ty * TM + i];
            #pragma unroll
            for (int j = 0; j < TN; j++) rb[j] = Bs[k][tx * TN + j];
            #pragma unroll
            for (int i = 0; i < TM; i++)
                #pragma unroll
                for (int j = 0; j < TN; j++)
                    acc[i][j] += ra[i] * rb[j];
        }
        __syncthreads();
    }
    #pragma unroll
    for (int i = 0; i < TM; i++) {
        long m = row0 + ty * TM + i;
        #pragma unroll
        for (int j = 0; j < TN; j++) {
            int n = col0 + tx * TN + j;
            float v = acc[i][j] * alpha;
            if (bias) v += bias[n];
            if (ACT == 1) v = 0.5f * v * (1.0f + erff(v * 0.7071067811865476f));
            C[m * ldc + n] = v;
        }
    }
}

// ---------------- generic SGEMM, NT: C = alpha*(A@B^T) -----------------------
// A: [M,K] lda   B: [N,K] ldb   C: [M,N] ldc. Batched like above.
template<int BM, int BN, int BK, int TM, int TN>
__global__ void __launch_bounds__((BM/TM)*(BN/TN))
sgemm_nt(const float* __restrict__ A, const float* __restrict__ Bm,
         float* __restrict__ C,
         int M, int N, int K, int lda, int ldb, int ldc, float alpha,
         long sAb, long sAh, long sBb, long sBh, long sCb, long sCh, int Hh) {
    constexpr int THREADS = (BM/TM)*(BN/TN);
    if (Hh > 0) {
        int z = blockIdx.z;
        int bb = z / Hh, hh = z % Hh;
        A  += (long)bb * sAb + (long)hh * sAh;
        Bm += (long)bb * sBb + (long)hh * sBh;
        C  += (long)bb * sCb + (long)hh * sCh;
    }
    __shared__ float As[BK][BM];
    __shared__ float Bs[BK][BN];
    int tid = threadIdx.x;
    int tx = tid % (BN / TN);
    int ty = tid / (BN / TN);
    int row0 = blockIdx.y * BM;
    int col0 = blockIdx.x * BN;
    float acc[TM][TN] = {};
    constexpr int AVEC = BM * BK / (4 * THREADS);
    constexpr int BVEC = BN * BK / (4 * THREADS);
    for (int k0 = 0; k0 < K; k0 += BK) {
        #pragma unroll
        for (int i = 0; i < AVEC; i++) {
            int idx = tid + i * THREADS;
            int m  = idx / (BK / 4);
            int kk = (idx % (BK / 4)) * 4;
            float4 v = *(const float4*)&A[(long)(row0 + m) * lda + k0 + kk];
            As[kk + 0][m] = v.x; As[kk + 1][m] = v.y;
            As[kk + 2][m] = v.z; As[kk + 3][m] = v.w;
        }
        #pragma unroll
        for (int i = 0; i < BVEC; i++) {
            int idx = tid + i * THREADS;
            int n  = idx / (BK / 4);
            int kk = (idx % (BK / 4)) * 4;
            float4 v = *(const float4*)&Bm[(long)(col0 + n) * ldb + k0 + kk];
            Bs[kk + 0][n] = v.x; Bs[kk + 1][n] = v.y;
            Bs[kk + 2][n] = v.z; Bs[kk + 3][n] = v.w;
        }
        __syncthreads();
        #pragma unroll
        for (int k = 0; k < BK; k++) {
            float ra[TM], rb[TN];
            #pragma unroll
            for (int i = 0; i < TM; i++) ra[i] = As[k][ty * TM + i];
            #pragma unroll
            for (int j = 0; j < TN; j++) rb[j] = Bs[k][tx * TN + j];
            #pragma unroll
            for (int i = 0; i < TM; i++)
                #pragma unroll
                for (int j = 0; j < TN; j++)
                    acc[i][j] += ra[i] * rb[j];
        }
        __syncthreads();
    }
    #pragma unroll
    for (int i = 0; i < TM; i++) {
        long m = row0 + ty * TM + i;
        #pragma unroll
        for (int j = 0; j < TN; j++) {
            int n = col0 + tx * TN + j;
            C[m * ldc + n] = acc[i][j] * alpha;
        }
    }
}

// ---------------- row softmax over 2048 columns ------------------------------
__global__ void softmax_rows(float* __restrict__ p) {
    __shared__ float sm[32];
    float* pr = p + (long)blockIdx.x * SS;
    int t = threadIdx.x;
    float4 a = ((float4*)pr)[t];
    float4 b = ((float4*)pr)[t + 256];
    float mx = fmaxf(fmaxf(fmaxf(a.x, a.y), fmaxf(a.z, a.w)),
                     fmaxf(fmaxf(b.x, b.y), fmaxf(b.z, b.w)));
    mx = block_max256(mx, sm);
    a.x = expf(a.x - mx); a.y = expf(a.y - mx);
    a.z = expf(a.z - mx); a.w = expf(a.w - mx);
    b.x = expf(b.x - mx); b.y = expf(b.y - mx);
    b.z = expf(b.z - mx); b.w = expf(b.w - mx);
    float s = a.x + a.y + a.z + a.w + b.x + b.y + b.z + b.w;
    s = block_sum256(s, sm);
    float inv = 1.f / s;
    a.x *= inv; a.y *= inv; a.z *= inv; a.w *= inv;
    b.x *= inv; b.y *= inv; b.z *= inv; b.w *= inv;
    ((float4*)pr)[t] = a;
    ((float4*)pr)[t + 256] = b;
}

// ---------------- launch -----------------------------------------------------
extern "C" void kernel_launch(void* const* d_in, const int* in_sizes, int n_in,
                              void* d_out, int out_size) {
    const float* x   = (const float*)d_in[0];
    const float* Wq  = (const float*)d_in[1];
    const float* bq  = (const float*)d_in[2];
    const float* Wk  = (const float*)d_in[3];
    const float* bk  = (const float*)d_in[4];
    const float* Wv  = (const float*)d_in[5];
    const float* bv  = (const float*)d_in[6];
    const float* Wo  = (const float*)d_in[7];
    const float* bo  = (const float*)d_in[8];
    const float* W1  = (const float*)d_in[9];
    const float* b1  = (const float*)d_in[10];
    const float* W2  = (const float*)d_in[11];
    const float* b2  = (const float*)d_in[12];
    const float* g1  = (const float*)d_in[13];
    const float* be1 = (const float*)d_in[14];
    const float* g2  = (const float*)d_in[15];
    const float* be2 = (const float*)d_in[16];
    float* out = (float*)d_out;

    float *h, *wt, *bt, *qkv, *sc, *o, *a, *h2, *f;
    cudaGetSymbolAddress((void**)&h,   g_h);
    cudaGetSymbolAddress((void**)&wt,  g_wqkv);
    cudaGetSymbolAddress((void**)&bt,  g_bqkv);
    cudaGetSymbolAddress((void**)&qkv, g_qkv);
    cudaGetSymbolAddress((void**)&sc,  g_sc);
    cudaGetSymbolAddress((void**)&o,   g_o);
    cudaGetSymbolAddress((void**)&a,   g_a);
    cudaGetSymbolAddress((void**)&h2,  g_h2);
    cudaGetSymbolAddress((void**)&f,   g_f);

    const long SSl = (long)SS * SS;

    // 1. LN1
    ln_kernel<<<NTOK, 256>>>(x, g1, be1, h);

    // 2. repack QKV weights/bias
    repack_kernel<<<(DD * 3 * DD + 255) / 256, 256>>>(Wq, Wk, Wv, bq, bk, bv, wt, bt);

    // 3. fused QKV GEMM: [8192,768] @ [768,2304]
    sgemm_nn<128,128,16,8,8,0><<<dim3(3*DD/128, NTOK/128, 1), 256>>>(
        h, wt, bt, qkv, NTOK, 3*DD, DD, DD, 3*DD, 3*DD, 1.f,
        0,0,0,0,0,0, 0);

    // 4. scores = (Q @ K^T) / 8, batched over (b,h)
    sgemm_nt<128,128,16,8,8><<<dim3(SS/128, SS/128, BB*HH), 256>>>(
        qkv /*Q*/, qkv + DD /*K*/, sc,
        SS, SS, HD, 3*DD, 3*DD, SS, 0.125f,
        (long)SS*3*DD, 64, (long)SS*3*DD, 64, (long)HH*SSl, SSl, HH);

    // 5. softmax over rows
    softmax_rows<<<BB*HH*SS, 256>>>(sc);

    // 6. O = P @ V, batched over (b,h); writes [b,s,h,e] layout
    sgemm_nn<128,64,16,8,4,0><<<dim3(1, SS/128, BB*HH), 256>>>(
        sc, qkv + 2*DD /*V*/, nullptr, o,
        SS, HD, SS, SS, 3*DD, DD, 1.f,
        (long)HH*SSl, SSl, (long)SS*3*DD, 64, (long)SS*DD, 64, HH);

    // 7. a = O @ Wo + bo
    sgemm_nn<128,128,16,8,8,0><<<dim3(DD/128, NTOK/128, 1), 256>>>(
        o, Wo, bo, a, NTOK, DD, DD, DD, DD, DD, 1.f,
        0,0,0,0,0,0, 0);

    // 8. LN2
    ln_kernel<<<NTOK, 256>>>(a, g2, be2, h2);

    // 9. f = gelu(h2 @ W1 + b1)
    sgemm_nn<128,128,16,8,8,1><<<dim3(FF/128, NTOK/128, 1), 256>>>(
        h2, W1, b1, f, NTOK, FF, DD, DD, FF, FF, 1.f,
        0,0,0,0,0,0, 0);

    // 10. out = f @ W2 + b2
    sgemm_nn<128,128,16,8,8,0><<<dim3(DD/128, NTOK/128, 1), 256>>>(
        f, W2, b2, out, NTOK, DD, FF, FF, DD, DD, 1.f,
        0,0,0,0,0,0, 0);
}

// round 2
// speedup vs baseline: 3.2074x; 3.2074x over previous
#include <cuda_runtime.h>
#include <cuda_bf16.h>
#include <math.h>
#include <stdint.h>

// Problem constants
#define BB 4
#define SS 2048
#define DD 768
#define HH 12
#define HD 64
#define FF 3072
#define NTOK (BB*SS)          // 8192
#define EPS 1e-5f

// ---------------- scratch (static device globals; no allocation) -------------
__device__ float g_h   [(size_t)NTOK*DD];          // LN1 out (tf32)
__device__ float g_wqkv[(size_t)DD*3*DD];          // repacked [D, 3D] weights (tf32)
__device__ float g_bqkv[3*DD];                     // repacked bias
__device__ float g_qkv [(size_t)NTOK*3*DD];        // [n, 2304] q|k|v (tf32)
__device__ float g_sc  [(size_t)BB*HH*SS*SS];      // scores / probs
__device__ float g_o   [(size_t)NTOK*DD];          // attention out [b,s,h,e] (tf32)
__device__ float g_a   [(size_t)NTOK*DD];          // after Wo
__device__ float g_h2  [(size_t)NTOK*DD];          // LN2 out (tf32)
__device__ float g_f   [(size_t)NTOK*FF];          // gelu(FFN1) (tf32)
__device__ float g_wo  [(size_t)DD*DD];            // tf32 copies of weights
__device__ float g_w1  [(size_t)DD*FF];
__device__ float g_w2  [(size_t)FF*DD];

// ---------------- helpers ----------------------------------------------------
__device__ __forceinline__ float tf32r(float x) {
    uint32_t u;
    asm("cvt.rna.tf32.f32 %0, %1;" : "=r"(u) : "f"(x));
    return __uint_as_float(u);
}

__device__ __forceinline__ void cp16(void* s, const void* g) {
    uint32_t sa = (uint32_t)__cvta_generic_to_shared(s);
    asm volatile("cp.async.cg.shared.global [%0], [%1], 16;\n" :: "r"(sa), "l"(g));
}
__device__ __forceinline__ void cp_commit() {
    asm volatile("cp.async.commit_group;\n" ::: "memory");
}

__device__ __forceinline__ void mma_tf32(float* c, const uint32_t* a, const uint32_t* b) {
    asm volatile(
        "mma.sync.aligned.m16n8k8.row.col.f32.tf32.tf32.f32 "
        "{%0,%1,%2,%3}, {%4,%5,%6,%7}, {%8,%9}, {%0,%1,%2,%3};\n"
        : "+f"(c[0]), "+f"(c[1]), "+f"(c[2]), "+f"(c[3])
        : "r"(a[0]), "r"(a[1]), "r"(a[2]), "r"(a[3]), "r"(b[0]), "r"(b[1]));
}

// ---------------- reductions -------------------------------------------------
__device__ __forceinline__ float block_sum256(float v, float* sm) {
    __syncthreads();
    #pragma unroll
    for (int o = 16; o > 0; o >>= 1) v += __shfl_xor_sync(0xffffffffu, v, o);
    int lane = threadIdx.x & 31, w = threadIdx.x >> 5;
    if (lane == 0) sm[w] = v;
    __syncthreads();
    if (w == 0) {
        v = (lane < 8) ? sm[lane] : 0.f;
        #pragma unroll
        for (int o = 4; o > 0; o >>= 1) v += __shfl_xor_sync(0xffffffffu, v, o);
        if (lane == 0) sm[0] = v;
    }
    __syncthreads();
    return sm[0];
}

__device__ __forceinline__ float block_max256(float v, float* sm) {
    __syncthreads();
    #pragma unroll
    for (int o = 16; o > 0; o >>= 1) v = fmaxf(v, __shfl_xor_sync(0xffffffffu, v, o));
    int lane = threadIdx.x & 31, w = threadIdx.x >> 5;
    if (lane == 0) sm[w] = v;
    __syncthreads();
    if (w == 0) {
        v = (lane < 8) ? sm[lane] : -3.4e38f;
        #pragma unroll
        for (int o = 4; o > 0; o >>= 1) v = fmaxf(v, __shfl_xor_sync(0xffffffffu, v, o));
        if (lane == 0) sm[0] = v;
    }
    __syncthreads();
    return sm[0];
}

// ---------------- LayerNorm (row = 768, block = 256), tf32-rounded out -------
__global__ void ln_kernel(const float* __restrict__ x, const float* __restrict__ g,
                          const float* __restrict__ be, float* __restrict__ out) {
    __shared__ float sm[32];
    long row = blockIdx.x;
    const float* xr = x + row * DD;
    int t = threadIdx.x;
    float v0 = xr[t], v1 = xr[t + 256], v2 = xr[t + 512];
    float mu = block_sum256(v0 + v1 + v2, sm) * (1.f / DD);
    float d0 = v0 - mu, d1 = v1 - mu, d2 = v2 - mu;
    float var = block_sum256(d0*d0 + d1*d1 + d2*d2, sm) * (1.f / DD);
    float r = rsqrtf(var + EPS);
    float* o = out + row * DD;
    o[t]       = tf32r(d0 * r * g[t]       + be[t]);
    o[t + 256] = tf32r(d1 * r * g[t + 256] + be[t + 256]);
    o[t + 512] = tf32r(d2 * r * g[t + 512] + be[t + 512]);
}

// ---------------- weight repack: [H,D,HD]x3 -> [D, 3D] (tf32) ----------------
__global__ void repack_kernel(const float* __restrict__ Wq, const float* __restrict__ Wk,
                              const float* __restrict__ Wv, const float* __restrict__ bq,
                              const float* __restrict__ bk, const float* __restrict__ bv,
                              float* __restrict__ Wt, float* __restrict__ bt) {
    int idx = blockIdx.x * blockDim.x + threadIdx.x;
    if (idx < DD * 3 * DD) {
        int d = idx / (3 * DD);
        int c = idx % (3 * DD);
        int p = c / DD, r = c % DD;
        int h = r / HD, e = r % HD;
        const float* W = (p == 0) ? Wq : (p == 1) ? Wk : Wv;
        Wt[idx] = tf32r(W[((long)h * DD + d) * HD + e]);
    }
    if (idx < 3 * DD) {
        int p = idx / DD, r = idx % DD;
        int h = r / HD, e = r % HD;
        const float* b = (p == 0) ? bq : (p == 1) ? bk : bv;
        bt[idx] = b[h * HD + e];
    }
}

// ---------------- tf32-convert Wo/W1/W2 --------------------------------------
__global__ void cvt_weights(const float* __restrict__ Wo, const float* __restrict__ W1,
                            const float* __restrict__ W2, float* __restrict__ wo,
                            float* __restrict__ w1, float* __restrict__ w2) {
    long idx = (long)blockIdx.x * blockDim.x + threadIdx.x;
    const long s0 = (long)DD * DD;
    const long s1 = (long)DD * FF;
    if (idx < s0)               wo[idx] = tf32r(Wo[idx]);
    else if (idx < s0 + s1)     w1[idx - s0] = tf32r(W1[idx - s0]);
    else if (idx < s0 + 2*s1)   w2[idx - s0 - s1] = tf32r(W2[idx - s0 - s1]);
}

// ---------------- tensor-core GEMM -------------------------------------------
// C = alpha * A @ op(B) + bias, optional exact GELU, optional tf32-round of out.
// A: [M,K] row-major (lda). TRANSB=0: B [K,N] (ldb=N-stride); TRANSB=1: B [N,K].
// 256 threads, 8 warps as 4(m) x 2(n); warp tile (BM/4) x (BN/2); mma m16n8k8.
template<int BM, int BN, int BK, int TRANSB, int ACT, int ROUND>
__global__ void __launch_bounds__(256)
mma_gemm(const float* __restrict__ A, const float* __restrict__ B,
         const float* __restrict__ bias, float* __restrict__ C,
         int M, int N, int K, int lda, int ldb, int ldc, float alpha,
         long sAb, long sAh, long sBb, long sBh, long sCb, long sCh, int Hh) {
    if (Hh > 0) {
        int z = blockIdx.z;
        int bb = z / Hh, hh = z % Hh;
        A += (long)bb * sAb + (long)hh * sAh;
        B += (long)bb * sBb + (long)hh * sBh;
        C += (long)bb * sCb + (long)hh * sCh;
    }
    constexpr int ASTR = BK + 4;                       // As row stride (floats)
    constexpr int BSTR = TRANSB ? (BK + 4) : (BN + 8); // Bs row stride
    constexpr int ASTG = BM * ASTR;
    constexpr int BSTG = TRANSB ? BN * (BK + 4) : BK * (BN + 8);
    extern __shared__ float smem[];
    float* As = smem;
    float* Bs = smem + 2 * ASTG;

    const int tid  = threadIdx.x;
    const int lane = tid & 31;
    const int wid  = tid >> 5;
    const int wm = (wid >> 1) * (BM / 4);  // warp m offset
    const int wn = (wid & 1) * (BN / 2);   // warp n offset
    constexpr int MI = BM / 4 / 16;        // m-atoms per warp (2)
    constexpr int NI = BN / 2 / 8;         // n-atoms per warp (8 or 4)

    const int row0 = blockIdx.y * BM;
    const int col0 = blockIdx.x * BN;
    const int KT = K / BK;

    float acc[MI][NI][4] = {};

    auto load_tile = [&](int kt, int st) {
        const int k0 = kt * BK;
        // A: BM x BK, 16B vectors
        constexpr int AV = BM * BK / 4 / 256;
        #pragma unroll
        for (int i = 0; i < AV; i++) {
            int idx = tid + i * 256;
            int m  = idx / (BK / 4);
            int kg = idx % (BK / 4);
            cp16(&As[st * ASTG + m * ASTR + kg * 4],
                 &A[(long)(row0 + m) * lda + k0 + kg * 4]);
        }
        if (TRANSB) {
            // B [N,K] row-major -> Bs[n][k] direct copy
            constexpr int BV = BN * BK / 4 / 256;
            #pragma unroll
            for (int i = 0; i < BV; i++) {
                int idx = tid + i * 256;
                int n  = idx / (BK / 4);
                int kg = idx % (BK / 4);
                cp16(&Bs[st * BSTG + n * BSTR + kg * 4],
                     &B[(long)(col0 + n) * ldb + k0 + kg * 4]);
            }
        } else {
            // B [K,N] row-major -> Bs[k][n] direct copy
            constexpr int BV = BK * BN / 4 / 256;
            #pragma unroll
            for (int i = 0; i < BV; i++) {
                int idx = tid + i * 256;
                int k  = idx / (BN / 4);
                int ng = idx % (BN / 4);
                cp16(&Bs[st * BSTG + k * BSTR + ng * 4],
                     &B[(long)(k0 + k) * ldb + col0 + ng * 4]);
            }
        }
        cp_commit();
    };

    load_tile(0, 0);
    for (int kt = 0; kt < KT; kt++) {
        if (kt + 1 < KT) {
            load_tile(kt + 1, (kt + 1) & 1);
            asm volatile("cp.async.wait_group 1;\n" ::: "memory");
        } else {
            asm volatile("cp.async.wait_group 0;\n" ::: "memory");
        }
        __syncthreads();

        const float* AsS = As + (kt & 1) * ASTG;
        const float* BsS = Bs + (kt & 1) * BSTG;
        #pragma unroll
        for (int k8 = 0; k8 < BK; k8 += 8) {
            uint32_t af[MI][4];
            #pragma unroll
            for (int mi = 0; mi < MI; mi++) {
                int r = wm + mi * 16 + (lane >> 2);
                int c = k8 + (lane & 3);
                af[mi][0] = __float_as_uint(AsS[r * ASTR + c]);
                af[mi][1] = __float_as_uint(AsS[(r + 8) * ASTR + c]);
                af[mi][2] = __float_as_uint(AsS[r * ASTR + c + 4]);
                af[mi][3] = __float_as_uint(AsS[(r + 8) * ASTR + c + 4]);
            }
            uint32_t bf[NI][2];
            #pragma unroll
            for (int ni = 0; ni < NI; ni++) {
                int n = wn + ni * 8 + (lane >> 2);
                if (TRANSB) {
                    bf[ni][0] = __float_as_uint(BsS[n * BSTR + k8 + (lane & 3)]);
                    bf[ni][1] = __float_as_uint(BsS[n * BSTR + k8 + 4 + (lane & 3)]);
                } else {
                    bf[ni][0] = __float_as_uint(BsS[(k8 + (lane & 3)) * BSTR + n]);
                    bf[ni][1] = __float_as_uint(BsS[(k8 + 4 + (lane & 3)) * BSTR + n]);
                }
            }
            #pragma unroll
            for (int mi = 0; mi < MI; mi++)
                #pragma unroll
                for (int ni = 0; ni < NI; ni++)
                    mma_tf32(acc[mi][ni], af[mi], bf[ni]);
        }
        __syncthreads();
    }

    // epilogue
    #pragma unroll
    for (int mi = 0; mi < MI; mi++) {
        long m = row0 + wm + mi * 16 + (lane >> 2);
        #pragma unroll
        for (int ni = 0; ni < NI; ni++) {
            int n = col0 + wn + ni * 8 + (lane & 3) * 2;
            float b0 = 0.f, b1 = 0.f;
            if (bias) { b0 = bias[n]; b1 = bias[n + 1]; }
            float v[4];
            #pragma unroll
            for (int j = 0; j < 4; j++) v[j] = acc[mi][ni][j] * alpha;
            v[0] += b0; v[1] += b1; v[2] += b0; v[3] += b1;
            if (ACT == 1) {
                #pragma unroll
                for (int j = 0; j < 4; j++)
                    v[j] = 0.5f * v[j] * (1.0f + erff(v[j] * 0.7071067811865476f));
            }
            if (ROUND == 1) {
                #pragma unroll
                for (int j = 0; j < 4; j++) v[j] = tf32r(v[j]);
            }
            *(float2*)&C[m * ldc + n]       = make_float2(v[0], v[1]);
            *(float2*)&C[(m + 8) * ldc + n] = make_float2(v[2], v[3]);
        }
    }
}

// ---------------- row softmax over 2048 columns (tf32-rounded out) -----------
__global__ void softmax_rows(float* __restrict__ p) {
    __shared__ float sm[32];
    float* pr = p + (long)blockIdx.x * SS;
    int t = threadIdx.x;
    float4 a = ((float4*)pr)[t];
    float4 b = ((float4*)pr)[t + 256];
    float mx = fmaxf(fmaxf(fmaxf(a.x, a.y), fmaxf(a.z, a.w)),
                     fmaxf(fmaxf(b.x, b.y), fmaxf(b.z, b.w)));
    mx = block_max256(mx, sm);
    a.x = expf(a.x - mx); a.y = expf(a.y - mx);
    a.z = expf(a.z - mx); a.w = expf(a.w - mx);
    b.x = expf(b.x - mx); b.y = expf(b.y - mx);
    b.z = expf(b.z - mx); b.w = expf(b.w - mx);
    float s = a.x + a.y + a.z + a.w + b.x + b.y + b.z + b.w;
    s = block_sum256(s, sm);
    float inv = 1.f / s;
    a.x = tf32r(a.x * inv); a.y = tf32r(a.y * inv);
    a.z = tf32r(a.z * inv); a.w = tf32r(a.w * inv);
    b.x = tf32r(b.x * inv); b.y = tf32r(b.y * inv);
    b.z = tf32r(b.z * inv); b.w = tf32r(b.w * inv);
    ((float4*)pr)[t] = a;
    ((float4*)pr)[t + 256] = b;
}

// ---------------- launch -----------------------------------------------------
extern "C" void kernel_launch(void* const* d_in, const int* in_sizes, int n_in,
                              void* d_out, int out_size) {
    const float* x   = (const float*)d_in[0];
    const float* Wq  = (const float*)d_in[1];
    const float* bq  = (const float*)d_in[2];
    const float* Wk  = (const float*)d_in[3];
    const float* bk  = (const float*)d_in[4];
    const float* Wv  = (const float*)d_in[5];
    const float* bv  = (const float*)d_in[6];
    const float* Wo  = (const float*)d_in[7];
    const float* bo  = (const float*)d_in[8];
    const float* W1  = (const float*)d_in[9];
    const float* b1  = (const float*)d_in[10];
    const float* W2  = (const float*)d_in[11];
    const float* b2  = (const float*)d_in[12];
    const float* g1  = (const float*)d_in[13];
    const float* be1 = (const float*)d_in[14];
    const float* g2  = (const float*)d_in[15];
    const float* be2 = (const float*)d_in[16];
    float* out = (float*)d_out;

    float *h, *wt, *bt, *qkv, *sc, *o, *a, *h2, *f, *wo, *w1, *w2;
    cudaGetSymbolAddress((void**)&h,   g_h);
    cudaGetSymbolAddress((void**)&wt,  g_wqkv);
    cudaGetSymbolAddress((void**)&bt,  g_bqkv);
    cudaGetSymbolAddress((void**)&qkv, g_qkv);
    cudaGetSymbolAddress((void**)&sc,  g_sc);
    cudaGetSymbolAddress((void**)&o,   g_o);
    cudaGetSymbolAddress((void**)&a,   g_a);
    cudaGetSymbolAddress((void**)&h2,  g_h2);
    cudaGetSymbolAddress((void**)&f,   g_f);
    cudaGetSymbolAddress((void**)&wo,  g_wo);
    cudaGetSymbolAddress((void**)&w1,  g_w1);
    cudaGetSymbolAddress((void**)&w2,  g_w2);

    const long SSl = (long)SS * SS;

    // kernel instantiations + dynamic smem sizes
    auto* Gqkv  = mma_gemm<128,128,32,0,0,1>;  const int SMqkv  = 71680;
    auto* Gqkt  = mma_gemm<128,128,32,1,0,0>;  const int SMqkt  = 73728;
    auto* Gpv   = mma_gemm<128, 64,32,0,0,1>;  const int SMpv   = 55296;
    auto* Gnn   = mma_gemm<128,128,32,0,0,0>;  const int SMnn   = 71680;
    auto* Gff1  = mma_gemm<128,128,32,0,1,1>;  const int SMff1  = 71680;
    cudaFuncSetAttribute(Gqkv, cudaFuncAttributeMaxDynamicSharedMemorySize, SMqkv);
    cudaFuncSetAttribute(Gqkt, cudaFuncAttributeMaxDynamicSharedMemorySize, SMqkt);
    cudaFuncSetAttribute(Gpv,  cudaFuncAttributeMaxDynamicSharedMemorySize, SMpv);
    cudaFuncSetAttribute(Gnn,  cudaFuncAttributeMaxDynamicSharedMemorySize, SMnn);
    cudaFuncSetAttribute(Gff1, cudaFuncAttributeMaxDynamicSharedMemorySize, SMff1);

    // 1. LN1 (tf32 out)
    ln_kernel<<<NTOK, 256>>>(x, g1, be1, h);

    // 2. repack QKV weights/bias (tf32), convert Wo/W1/W2 (tf32)
    repack_kernel<<<(DD * 3 * DD + 255) / 256, 256>>>(Wq, Wk, Wv, bq, bk, bv, wt, bt);
    {
        long tot = (long)DD*DD + 2L*DD*FF;
        cvt_weights<<<(int)((tot + 255) / 256), 256>>>(Wo, W1, W2, wo, w1, w2);
    }

    // 3. fused QKV GEMM: [8192,768] @ [768,2304]
    Gqkv<<<dim3(3*DD/128, NTOK/128, 1), 256, SMqkv>>>(
        h, wt, bt, qkv, NTOK, 3*DD, DD, DD, 3*DD, 3*DD, 1.f,
        0,0,0,0,0,0, 0);

    // 4. scores = (Q @ K^T) / 8, batched over (b,h)
    Gqkt<<<dim3(SS/128, SS/128, BB*HH), 256, SMqkt>>>(
        qkv /*Q*/, qkv + DD /*K*/, nullptr, sc,
        SS, SS, HD, 3*DD, 3*DD, SS, 0.125f,
        (long)SS*3*DD, 64, (long)SS*3*DD, 64, (long)HH*SSl, SSl, HH);

    // 5. softmax over rows (tf32 out)
    softmax_rows<<<BB*HH*SS, 256>>>(sc);

    // 6. O = P @ V, batched over (b,h); writes [b,s,h,e] layout (tf32 out)
    Gpv<<<dim3(1, SS/128, BB*HH), 256, SMpv>>>(
        sc, qkv + 2*DD /*V*/, nullptr, o,
        SS, HD, SS, SS, 3*DD, DD, 1.f,
        (long)HH*SSl, SSl, (long)SS*3*DD, 64, (long)SS*DD, 64, HH);

    // 7. a = O @ Wo + bo
    Gnn<<<dim3(DD/128, NTOK/128, 1), 256, SMnn>>>(
        o, wo, bo, a, NTOK, DD, DD, DD, DD, DD, 1.f,
        0,0,0,0,0,0, 0);

    // 8. LN2 (tf32 out)
    ln_kernel<<<NTOK, 256>>>(a, g2, be2, h2);

    // 9. f = gelu(h2 @ W1 + b1) (tf32 out)
    Gff1<<<dim3(FF/128, NTOK/128, 1), 256, SMff1>>>(
        h2, w1, b1, f, NTOK, FF, DD, DD, FF, FF, 1.f,
        0,0,0,0,0,0, 0);

    // 10. out = f @ W2 + b2
    Gnn<<<dim3(DD/128, NTOK/128, 1), 256, SMnn>>>(
        f, w2, b2, out, NTOK, DD, FF, FF, DD, DD, 1.f,
        0,0,0,0,0,0, 0);
}

// round 3
// speedup vs baseline: 3.6628x; 1.1420x over previous
#include <cuda_runtime.h>
#include <cuda_bf16.h>
#include <math.h>
#include <stdint.h>

// Problem constants
#define BB 4
#define SS 2048
#define DD 768
#define HH 12
#define HD 64
#define FF 3072
#define NTOK (BB*SS)          // 8192
#define EPS 1e-5f

// ---------------- scratch (static device globals; no allocation) -------------
__device__ float g_h   [(size_t)NTOK*DD];          // LN1 out (tf32)
__device__ float g_wqkv[(size_t)DD*3*DD];          // repacked [D, 3D] weights (tf32)
__device__ float g_bqkv[3*DD];                     // repacked bias
__device__ float g_qkv [(size_t)NTOK*3*DD];        // [n, 2304] q|k|v (tf32)
__device__ float g_o   [(size_t)NTOK*DD];          // attention out [b,s,h,e] (tf32)
__device__ float g_a   [(size_t)NTOK*DD];          // after Wo
__device__ float g_h2  [(size_t)NTOK*DD];          // LN2 out (tf32)
__device__ float g_f   [(size_t)NTOK*FF];          // gelu(FFN1) (tf32)
__device__ float g_wo  [(size_t)DD*DD];            // tf32 copies of weights
__device__ float g_w1  [(size_t)DD*FF];
__device__ float g_w2  [(size_t)FF*DD];

// ---------------- helpers ----------------------------------------------------
__device__ __forceinline__ float tf32r(float x) {
    uint32_t u;
    asm("cvt.rna.tf32.f32 %0, %1;" : "=r"(u) : "f"(x));
    return __uint_as_float(u);
}

__device__ __forceinline__ void cp16(void* s, const void* g) {
    uint32_t sa = (uint32_t)__cvta_generic_to_shared(s);
    asm volatile("cp.async.cg.shared.global [%0], [%1], 16;\n" :: "r"(sa), "l"(g));
}
__device__ __forceinline__ void cp_commit() {
    asm volatile("cp.async.commit_group;\n" ::: "memory");
}

__device__ __forceinline__ void mma_tf32(float* c, const uint32_t* a, const uint32_t* b) {
    asm volatile(
        "mma.sync.aligned.m16n8k8.row.col.f32.tf32.tf32.f32 "
        "{%0,%1,%2,%3}, {%4,%5,%6,%7}, {%8,%9}, {%0,%1,%2,%3};\n"
        : "+f"(c[0]), "+f"(c[1]), "+f"(c[2]), "+f"(c[3])
        : "r"(a[0]), "r"(a[1]), "r"(a[2]), "r"(a[3]), "r"(b[0]), "r"(b[1]));
}

// ---------------- reductions -------------------------------------------------
__device__ __forceinline__ float block_sum256(float v, float* sm) {
    __syncthreads();
    #pragma unroll
    for (int o = 16; o > 0; o >>= 1) v += __shfl_xor_sync(0xffffffffu, v, o);
    int lane = threadIdx.x & 31, w = threadIdx.x >> 5;
    if (lane == 0) sm[w] = v;
    __syncthreads();
    if (w == 0) {
        v = (lane < 8) ? sm[lane] : 0.f;
        #pragma unroll
        for (int o = 4; o > 0; o >>= 1) v += __shfl_xor_sync(0xffffffffu, v, o);
        if (lane == 0) sm[0] = v;
    }
    __syncthreads();
    return sm[0];
}

// ---------------- LayerNorm (row = 768, block = 256), tf32-rounded out -------
__global__ void ln_kernel(const float* __restrict__ x, const float* __restrict__ g,
                          const float* __restrict__ be, float* __restrict__ out) {
    __shared__ float sm[32];
    long row = blockIdx.x;
    const float* xr = x + row * DD;
    int t = threadIdx.x;
    float v0 = xr[t], v1 = xr[t + 256], v2 = xr[t + 512];
    float mu = block_sum256(v0 + v1 + v2, sm) * (1.f / DD);
    float d0 = v0 - mu, d1 = v1 - mu, d2 = v2 - mu;
    float var = block_sum256(d0*d0 + d1*d1 + d2*d2, sm) * (1.f / DD);
    float r = rsqrtf(var + EPS);
    float* o = out + row * DD;
    o[t]       = tf32r(d0 * r * g[t]       + be[t]);
    o[t + 256] = tf32r(d1 * r * g[t + 256] + be[t + 256]);
    o[t + 512] = tf32r(d2 * r * g[t + 512] + be[t + 512]);
}

// ---------------- weight repack: [H,D,HD]x3 -> [D, 3D] (tf32) ----------------
__global__ void repack_kernel(const float* __restrict__ Wq, const float* __restrict__ Wk,
                              const float* __restrict__ Wv, const float* __restrict__ bq,
                              const float* __restrict__ bk, const float* __restrict__ bv,
                              float* __restrict__ Wt, float* __restrict__ bt) {
    int idx = blockIdx.x * blockDim.x + threadIdx.x;
    if (idx < DD * 3 * DD) {
        int d = idx / (3 * DD);
        int c = idx % (3 * DD);
        int p = c / DD, r = c % DD;
        int h = r / HD, e = r % HD;
        const float* W = (p == 0) ? Wq : (p == 1) ? Wk : Wv;
        Wt[idx] = tf32r(W[((long)h * DD + d) * HD + e]);
    }
    if (idx < 3 * DD) {
        int p = idx / DD, r = idx % DD;
        int h = r / HD, e = r % HD;
        const float* b = (p == 0) ? bq : (p == 1) ? bk : bv;
        bt[idx] = b[h * HD + e];
    }
}

// ---------------- tf32-convert Wo/W1/W2 --------------------------------------
__global__ void cvt_weights(const float* __restrict__ Wo, const float* __restrict__ W1,
                            const float* __restrict__ W2, float* __restrict__ wo,
                            float* __restrict__ w1, float* __restrict__ w2) {
    long idx = (long)blockIdx.x * blockDim.x + threadIdx.x;
    const long s0 = (long)DD * DD;
    const long s1 = (long)DD * FF;
    if (idx < s0)               wo[idx] = tf32r(Wo[idx]);
    else if (idx < s0 + s1)     w1[idx - s0] = tf32r(W1[idx - s0]);
    else if (idx < s0 + 2*s1)   w2[idx - s0 - s1] = tf32r(W2[idx - s0 - s1]);
}

// ---------------- tensor-core GEMM (dense projections / FFN) -----------------
template<int BM, int BN, int BK, int TRANSB, int ACT, int ROUND>
__global__ void __launch_bounds__(256)
mma_gemm(const float* __restrict__ A, const float* __restrict__ B,
         const float* __restrict__ bias, float* __restrict__ C,
         int M, int N, int K, int lda, int ldb, int ldc, float alpha) {
    constexpr int ASTR = BK + 4;
    constexpr int BSTR = TRANSB ? (BK + 4) : (BN + 8);
    constexpr int ASTG = BM * ASTR;
    constexpr int BSTG = TRANSB ? BN * (BK + 4) : BK * (BN + 8);
    extern __shared__ float smem[];
    float* As = smem;
    float* Bs = smem + 2 * ASTG;

    const int tid  = threadIdx.x;
    const int lane = tid & 31;
    const int wid  = tid >> 5;
    const int wm = (wid >> 1) * (BM / 4);
    const int wn = (wid & 1) * (BN / 2);
    constexpr int MI = BM / 4 / 16;
    constexpr int NI = BN / 2 / 8;

    const int row0 = blockIdx.y * BM;
    const int col0 = blockIdx.x * BN;
    const int KT = K / BK;

    float acc[MI][NI][4] = {};

    auto load_tile = [&](int kt, int st) {
        const int k0 = kt * BK;
        constexpr int AV = BM * BK / 4 / 256;
        #pragma unroll
        for (int i = 0; i < AV; i++) {
            int idx = tid + i * 256;
            int m  = idx / (BK / 4);
            int kg = idx % (BK / 4);
            cp16(&As[st * ASTG + m * ASTR + kg * 4],
                 &A[(long)(row0 + m) * lda + k0 + kg * 4]);
        }
        if (TRANSB) {
            constexpr int BV = BN * BK / 4 / 256;
            #pragma unroll
            for (int i = 0; i < BV; i++) {
                int idx = tid + i * 256;
                int n  = idx / (BK / 4);
                int kg = idx % (BK / 4);
                cp16(&Bs[st * BSTG + n * BSTR + kg * 4],
                     &B[(long)(col0 + n) * ldb + k0 + kg * 4]);
            }
        } else {
            constexpr int BV = BK * BN / 4 / 256;
            #pragma unroll
            for (int i = 0; i < BV; i++) {
                int idx = tid + i * 256;
                int k  = idx / (BN / 4);
                int ng = idx % (BN / 4);
                cp16(&Bs[st * BSTG + k * BSTR + ng * 4],
                     &B[(long)(k0 + k) * ldb + col0 + ng * 4]);
            }
        }
        cp_commit();
    };

    load_tile(0, 0);
    for (int kt = 0; kt < KT; kt++) {
        if (kt + 1 < KT) {
            load_tile(kt + 1, (kt + 1) & 1);
            asm volatile("cp.async.wait_group 1;\n" ::: "memory");
        } else {
            asm volatile("cp.async.wait_group 0;\n" ::: "memory");
        }
        __syncthreads();

        const float* AsS = As + (kt & 1) * ASTG;
        const float* BsS = Bs + (kt & 1) * BSTG;
        #pragma unroll
        for (int k8 = 0; k8 < BK; k8 += 8) {
            uint32_t af[MI][4];
            #pragma unroll
            for (int mi = 0; mi < MI; mi++) {
                int r = wm + mi * 16 + (lane >> 2);
                int c = k8 + (lane & 3);
                af[mi][0] = __float_as_uint(AsS[r * ASTR + c]);
                af[mi][1] = __float_as_uint(AsS[(r + 8) * ASTR + c]);
                af[mi][2] = __float_as_uint(AsS[r * ASTR + c + 4]);
                af[mi][3] = __float_as_uint(AsS[(r + 8) * ASTR + c + 4]);
            }
            uint32_t bf[NI][2];
            #pragma unroll
            for (int ni = 0; ni < NI; ni++) {
                int n = wn + ni * 8 + (lane >> 2);
                if (TRANSB) {
                    bf[ni][0] = __float_as_uint(BsS[n * BSTR + k8 + (lane & 3)]);
                    bf[ni][1] = __float_as_uint(BsS[n * BSTR + k8 + 4 + (lane & 3)]);
                } else {
                    bf[ni][0] = __float_as_uint(BsS[(k8 + (lane & 3)) * BSTR + n]);
                    bf[ni][1] = __float_as_uint(BsS[(k8 + 4 + (lane & 3)) * BSTR + n]);
                }
            }
            #pragma unroll
            for (int mi = 0; mi < MI; mi++)
                #pragma unroll
                for (int ni = 0; ni < NI; ni++)
                    mma_tf32(acc[mi][ni], af[mi], bf[ni]);
        }
        __syncthreads();
    }

    #pragma unroll
    for (int mi = 0; mi < MI; mi++) {
        long m = row0 + wm + mi * 16 + (lane >> 2);
        #pragma unroll
        for (int ni = 0; ni < NI; ni++) {
            int n = col0 + wn + ni * 8 + (lane & 3) * 2;
            float b0 = 0.f, b1 = 0.f;
            if (bias) { b0 = bias[n]; b1 = bias[n + 1]; }
            float v[4];
            #pragma unroll
            for (int j = 0; j < 4; j++) v[j] = acc[mi][ni][j] * alpha;
            v[0] += b0; v[1] += b1; v[2] += b0; v[3] += b1;
            if (ACT == 1) {
                #pragma unroll
                for (int j = 0; j < 4; j++)
                    v[j] = 0.5f * v[j] * (1.0f + erff(v[j] * 0.7071067811865476f));
            }
            if (ROUND == 1) {
                #pragma unroll
                for (int j = 0; j < 4; j++) v[j] = tf32r(v[j]);
            }
            *(float2*)&C[m * ldc + n]       = make_float2(v[0], v[1]);
            *(float2*)&C[(m + 8) * ldc + n] = make_float2(v[2], v[3]);
        }
    }
}

// ---------------- fused flash attention --------------------------------------
// grid = (SS/128, BB*HH). 256 threads = 8 warps; warp w owns Q rows w*16..+15.
// Q tile [128,64] in smem (reused as P buffer), K/V tiles [64,64] double-buffered.
// exp2-based online softmax, 1/8 score scale folded into the exp2 constant.
#define FA_STR 68               // padded row stride (floats)
#define FA_QS  (128 * FA_STR)   // Q / P region (floats)
#define FA_KT  (64 * FA_STR)    // one K or V tile (floats)
#define FA_NT  (SS / 64)        // 32 kv tiles

__global__ void __launch_bounds__(256)
flash_attn(const float* __restrict__ qkv, float* __restrict__ out) {
    const int bh = blockIdx.y;
    const int b = bh / HH, h = bh % HH;
    const float* base = qkv + (long)b * SS * 3 * DD + h * HD;
    const float* Qg = base;
    const float* Kg = base + DD;
    const float* Vg = base + 2 * DD;
    const int q0 = blockIdx.x * 128;

    extern __shared__ float sm[];
    float* Qs = sm;                 // 128 x FA_STR (later: P buffer)
    float* Ks = sm + FA_QS;         // 2 x 64 x FA_STR
    float* Vs = sm + FA_QS + 2 * FA_KT;

    const int tid  = threadIdx.x;
    const int lane = tid & 31;
    const int wid  = tid >> 5;
    const int r = lane >> 2;        // 0..7
    const int q = lane & 3;         // 0..3
    const int wrow = wid * 16;
    float* Pw = Qs + wrow * FA_STR; // per-warp P region [16][FA_STR]

    auto load_kv = [&](int j, int st) {
        #pragma unroll
        for (int i = 0; i < 4; i++) {
            int idx = tid + i * 256;
            int row = idx >> 4;
            int c4 = (idx & 15) * 4;
            long gr = (long)(j * 64 + row) * 3 * DD + c4;
            cp16(&Ks[st * FA_KT + row * FA_STR + c4], &Kg[gr]);
            cp16(&Vs[st * FA_KT + row * FA_STR + c4], &Vg[gr]);
        }
        cp_commit();
    };

    // prologue: Q tile + first K/V tile
    #pragma unroll
    for (int i = 0; i < 8; i++) {
        int idx = tid + i * 256;
        int row = idx >> 4;
        int c4 = (idx & 15) * 4;
        cp16(&Qs[row * FA_STR + c4], &Qg[(long)(q0 + row) * 3 * DD + c4]);
    }
    cp_commit();
    load_kv(0, 0);
    asm volatile("cp.async.wait_group 1;\n" ::: "memory"); // Q group done
    __syncthreads();

    // Q fragments -> registers
    uint32_t af[8][4];
    #pragma unroll
    for (int k8 = 0; k8 < 8; k8++) {
        int c = k8 * 8 + q;
        af[k8][0] = __float_as_uint(Qs[(wrow + r) * FA_STR + c]);
        af[k8][1] = __float_as_uint(Qs[(wrow + r + 8) * FA_STR + c]);
        af[k8][2] = __float_as_uint(Qs[(wrow + r) * FA_STR + c + 4]);
        af[k8][3] = __float_as_uint(Qs[(wrow + r + 8) * FA_STR + c + 4]);
    }
    __syncthreads();   // Q region now reusable as P

    const float KSC = 0.18033688011112042f;  // 0.125 * log2(e)
    float m0 = -INFINITY, m1 = -INFINITY, l0 = 0.f, l1 = 0.f;
    float oacc[8][4] = {};

    for (int j = 0; j < FA_NT; j++) {
        if (j + 1 < FA_NT) {
            load_kv(j + 1, (j + 1) & 1);
            asm volatile("cp.async.wait_group 1;\n" ::: "memory");
        } else {
            asm volatile("cp.async.wait_group 0;\n" ::: "memory");
        }
        __syncthreads();

        const float* K0 = Ks + (j & 1) * FA_KT;
        const float* V0 = Vs + (j & 1) * FA_KT;

        // S = Q @ K^T  (raw scores; scale folded into exp2 constant)
        float sacc[8][4] = {};
        #pragma unroll
        for (int k8 = 0; k8 < 8; k8++) {
            #pragma unroll
            for (int ni = 0; ni < 8; ni++) {
                uint32_t bf[2];
                bf[0] = __float_as_uint(K0[(ni * 8 + r) * FA_STR + k8 * 8 + q]);
                bf[1] = __float_as_uint(K0[(ni * 8 + r) * FA_STR + k8 * 8 + 4 + q]);
                mma_tf32(sacc[ni], af[k8], bf);
            }
        }

        // online softmax
        float mx0 = -INFINITY, mx1 = -INFINITY;
        #pragma unroll
        for (int ni = 0; ni < 8; ni++) {
            mx0 = fmaxf(mx0, fmaxf(sacc[ni][0], sacc[ni][1]));
            mx1 = fmaxf(mx1, fmaxf(sacc[ni][2], sacc[ni][3]));
        }
        mx0 = fmaxf(mx0, __shfl_xor_sync(0xffffffffu, mx0, 1));
        mx0 = fmaxf(mx0, __shfl_xor_sync(0xffffffffu, mx0, 2));
        mx1 = fmaxf(mx1, __shfl_xor_sync(0xffffffffu, mx1, 1));
        mx1 = fmaxf(mx1, __shfl_xor_sync(0xffffffffu, mx1, 2));
        float nm0 = fmaxf(m0, mx0), nm1 = fmaxf(m1, mx1);
        float c0 = exp2f((m0 - nm0) * KSC), c1 = exp2f((m1 - nm1) * KSC);
        m0 = nm0; m1 = nm1;

        float rs0 = 0.f, rs1 = 0.f;
        #pragma unroll
        for (int ni = 0; ni < 8; ni++) {
            float p00 = exp2f((sacc[ni][0] - nm0) * KSC);
            float p01 = exp2f((sacc[ni][1] - nm0) * KSC);
            float p10 = exp2f((sacc[ni][2] - nm1) * KSC);
            float p11 = exp2f((sacc[ni][3] - nm1) * KSC);
            rs0 += p00 + p01; rs1 += p10 + p11;
            int c = ni * 8 + 2 * q;
            *(float2*)&Pw[r * FA_STR + c]       = make_float2(tf32r(p00), tf32r(p01));
            *(float2*)&Pw[(r + 8) * FA_STR + c] = make_float2(tf32r(p10), tf32r(p11));
        }
        rs0 += __shfl_xor_sync(0xffffffffu, rs0, 1);
        rs0 += __shfl_xor_sync(0xffffffffu, rs0, 2);
        rs1 += __shfl_xor_sync(0xffffffffu, rs1, 1);
        rs1 += __shfl_xor_sync(0xffffffffu, rs1, 2);
        l0 = l0 * c0 + rs0;
        l1 = l1 * c1 + rs1;
        #pragma unroll
        for (int ni = 0; ni < 8; ni++) {
            oacc[ni][0] *= c0; oacc[ni][1] *= c0;
            oacc[ni][2] *= c1; oacc[ni][3] *= c1;
        }
        __syncwarp();

        // O += P @ V
        #pragma unroll
        for (int k8 = 0; k8 < 8; k8++) {
            uint32_t pa[4];
            int c = k8 * 8 + q;
            pa[0] = __float_as_uint(Pw[r * FA_STR + c]);
            pa[1] = __float_as_uint(Pw[(r + 8) * FA_STR + c]);
            pa[2] = __float_as_uint(Pw[r * FA_STR + c + 4]);
            pa[3] = __float_as_uint(Pw[(r + 8) * FA_STR + c + 4]);
            #pragma unroll
            for (int ni = 0; ni < 8; ni++) {
                uint32_t bf[2];
                bf[0] = __float_as_uint(V0[(k8 * 8 + q) * FA_STR + ni * 8 + r]);
                bf[1] = __float_as_uint(V0[(k8 * 8 + 4 + q) * FA_STR + ni * 8 + r]);
                mma_tf32(oacc[ni], pa, bf);
            }
        }
        __syncthreads();
    }

    // epilogue: normalize and write [b, s, h*64+e] (tf32 out for Wo GEMM)
    float inv0 = 1.f / l0, inv1 = 1.f / l1;
    long row0 = (long)b * SS + q0 + wrow + r;
    #pragma unroll
    for (int ni = 0; ni < 8; ni++) {
        int col = h * HD + ni * 8 + 2 * q;
        *(float2*)&out[row0 * DD + col] =
            make_float2(tf32r(oacc[ni][0] * inv0), tf32r(oacc[ni][1] * inv0));
        *(float2*)&out[(row0 + 8) * DD + col] =
            make_float2(tf32r(oacc[ni][2] * inv1), tf32r(oacc[ni][3] * inv1));
    }
}

// ---------------- launch -----------------------------------------------------
extern "C" void kernel_launch(void* const* d_in, const int* in_sizes, int n_in,
                              void* d_out, int out_size) {
    const float* x   = (const float*)d_in[0];
    const float* Wq  = (const float*)d_in[1];
    const float* bq  = (const float*)d_in[2];
    const float* Wk  = (const float*)d_in[3];
    const float* bk  = (const float*)d_in[4];
    const float* Wv  = (const float*)d_in[5];
    const float* bv  = (const float*)d_in[6];
    const float* Wo  = (const float*)d_in[7];
    const float* bo  = (const float*)d_in[8];
    const float* W1  = (const float*)d_in[9];
    const float* b1  = (const float*)d_in[10];
    const float* W2  = (const float*)d_in[11];
    const float* b2  = (const float*)d_in[12];
    const float* g1  = (const float*)d_in[13];
    const float* be1 = (const float*)d_in[14];
    const float* g2  = (const float*)d_in[15];
    const float* be2 = (const float*)d_in[16];
    float* out = (float*)d_out;

    float *h, *wt, *bt, *qkv, *o, *a, *h2, *f, *wo, *w1, *w2;
    cudaGetSymbolAddress((void**)&h,   g_h);
    cudaGetSymbolAddress((void**)&wt,  g_wqkv);
    cudaGetSymbolAddress((void**)&bt,  g_bqkv);
    cudaGetSymbolAddress((void**)&qkv, g_qkv);
    cudaGetSymbolAddress((void**)&o,   g_o);
    cudaGetSymbolAddress((void**)&a,   g_a);
    cudaGetSymbolAddress((void**)&h2,  g_h2);
    cudaGetSymbolAddress((void**)&f,   g_f);
    cudaGetSymbolAddress((void**)&wo,  g_wo);
    cudaGetSymbolAddress((void**)&w1,  g_w1);
    cudaGetSymbolAddress((void**)&w2,  g_w2);

    auto* Gqkv  = mma_gemm<128,128,32,0,0,1>;  const int SMqkv  = 71680;
    auto* Gnn   = mma_gemm<128,128,32,0,0,0>;  const int SMnn   = 71680;
    auto* Gff1  = mma_gemm<128,128,32,0,1,1>;  const int SMff1  = 71680;
    const int SMfa = (FA_QS + 4 * FA_KT) * 4;  // 104448 bytes
    cudaFuncSetAttribute(Gqkv, cudaFuncAttributeMaxDynamicSharedMemorySize, SMqkv);
    cudaFuncSetAttribute(Gnn,  cudaFuncAttributeMaxDynamicSharedMemorySize, SMnn);
    cudaFuncSetAttribute(Gff1, cudaFuncAttributeMaxDynamicSharedMemorySize, SMff1);
    cudaFuncSetAttribute(flash_attn, cudaFuncAttributeMaxDynamicSharedMemorySize, SMfa);

    // 1. LN1 (tf32 out)
    ln_kernel<<<NTOK, 256>>>(x, g1, be1, h);

    // 2. repack QKV weights/bias (tf32), convert Wo/W1/W2 (tf32)
    repack_kernel<<<(DD * 3 * DD + 255) / 256, 256>>>(Wq, Wk, Wv, bq, bk, bv, wt, bt);
    {
        long tot = (long)DD*DD + 2L*DD*FF;
        cvt_weights<<<(int)((tot + 255) / 256), 256>>>(Wo, W1, W2, wo, w1, w2);
    }

    // 3. fused QKV GEMM: [8192,768] @ [768,2304] (tf32 out)
    Gqkv<<<dim3(3*DD/128, NTOK/128, 1), 256, SMqkv>>>(
        h, wt, bt, qkv, NTOK, 3*DD, DD, DD, 3*DD, 3*DD, 1.f);

    // 4. fused flash attention -> o in [b,s,h,e] layout (tf32 out)
    flash_attn<<<dim3(SS/128, BB*HH), 256, SMfa>>>(qkv, o);

    // 5. a = O @ Wo + bo
    Gnn<<<dim3(DD/128, NTOK/128, 1), 256, SMnn>>>(
        o, wo, bo, a, NTOK, DD, DD, DD, DD, DD, 1.f);

    // 6. LN2 (tf32 out)
    ln_kernel<<<NTOK, 256>>>(a, g2, be2, h2);

    // 7. f = gelu(h2 @ W1 + b1) (tf32 out)
    Gff1<<<dim3(FF/128, NTOK/128, 1), 256, SMff1>>>(
        h2, w1, b1, f, NTOK, FF, DD, DD, FF, FF, 1.f);

    // 8. out = f @ W2 + b2
    Gnn<<<dim3(DD/128, NTOK/128, 1), 256, SMnn>>>(
        f, w2, b2, out, NTOK, DD, FF, FF, DD, DD, 1.f);
}